// round 1
// baseline (speedup 1.0000x reference)
#include <cuda_runtime.h>
#include <math.h>

// Problem constants (fixed by reference)
#define BB 4
#define CC 64
#define HHH 64
#define WWW 64
#define LL 4096          // H*W
#define DD 128           // D_INNER
#define SS 16            // D_STATE
#define NCH 64           // number of scan chunks
#define TCH 64           // chunk length  (NCH*TCH == LL)

// ---- scratch (static device memory; no allocation allowed) ----
__device__ float g_t  [BB*LL*CC];   // after axial depthwise stage, [b,l,c]
__device__ float g_seq[BB*LL*CC];   // relu output (residual), [b,l,c]
__device__ float g_hn [BB*LL*CC];   // layernorm output, [b,l,c]
__device__ float g_xm [BB*LL*DD];   // in_proj first half
__device__ float g_z  [BB*LL*DD];   // in_proj second half
__device__ float g_xc [BB*LL*DD];   // conv1d+silu
__device__ float g_dt [BB*LL*DD];   // softplus(dt)
__device__ float g_Bc [BB*LL*SS];
__device__ float g_Cc [BB*LL*SS];
__device__ float g_y  [BB*LL*DD];   // scan output
__device__ float g_P  [BB*NCH*DD*SS]; // per-chunk decay product
__device__ float g_H  [BB*NCH*DD*SS]; // per-chunk end-state -> start-state

// ============================================================
// K1a: axial depthwise convs (3x1 + 1x3, groups=C) + residual + biases.
// Coalesced reads from NCHW; scattered (transposing) writes to [b,l,c].
// ============================================================
__global__ void k_axial(const float* __restrict__ x,
                        const float* __restrict__ whw, const float* __restrict__ whb,
                        const float* __restrict__ www, const float* __restrict__ wwb) {
    int bidx = blockIdx.x;            // B*C*16 = 4096 blocks
    int b  = bidx >> 10;
    int c  = (bidx >> 4) & 63;
    int hg = bidx & 15;
    int h  = (hg << 2) + (threadIdx.x >> 6);
    int w  = threadIdx.x & 63;
    const float* xb = x + ((b*CC + c)*HHH)*WWW;
    float x0  = xb[h*WWW + w];
    float xhm = (h > 0)       ? xb[(h-1)*WWW + w] : 0.f;
    float xhp = (h < HHH-1)   ? xb[(h+1)*WWW + w] : 0.f;
    float xwm = (w > 0)       ? xb[h*WWW + w - 1] : 0.f;
    float xwp = (w < WWW-1)   ? xb[h*WWW + w + 1] : 0.f;
    float t = x0
        + whw[c*3+0]*xhm + whw[c*3+1]*x0 + whw[c*3+2]*xhp + whb[c]
        + www[c*3+0]*xwm + www[c*3+1]*x0 + www[c*3+2]*xwp + wwb[c];
    g_t[((b*LL) + h*WWW + w)*CC + c] = t;
}

// ============================================================
// K1b: 1x1 conv (C->C) + bias + BN(eval) + ReLU + LayerNorm over C.
// 4 pixels x 64 channels per 256-thread block; conv_w staged transposed in smem.
// ============================================================
__global__ void k_conv1x1(const float* __restrict__ conv_w, const float* __restrict__ conv_b,
                          const float* __restrict__ bn_g, const float* __restrict__ bn_b,
                          const float* __restrict__ bn_m, const float* __restrict__ bn_v,
                          const float* __restrict__ ln_g, const float* __restrict__ ln_b) {
    __shared__ float cw[64*64];       // cw[in*64 + out]
    __shared__ float tsh[4][64];
    __shared__ float wsum[8], wsq[8];
    int tid = threadIdx.x;
    for (int i = tid; i < 4096; i += 256)
        cw[i] = conv_w[((i & 63) << 6) + (i >> 6)];
    int p = tid >> 6, c = tid & 63;
    int token = (blockIdx.x << 2) + p;
    tsh[p][c] = g_t[token*64 + c];
    __syncthreads();
    float acc = conv_b[c];
    #pragma unroll
    for (int k = 0; k < 64; k++) acc += cw[(k << 6) + c] * tsh[p][k];
    float r = (acc - bn_m[c]) * rsqrtf(bn_v[c] + 1e-5f) * bn_g[c] + bn_b[c];
    r = fmaxf(r, 0.f);
    g_seq[token*64 + c] = r;
    // LayerNorm over 64 channels (2 warps per pixel group)
    float s1 = r, s2 = r * r;
    #pragma unroll
    for (int o = 16; o; o >>= 1) {
        s1 += __shfl_xor_sync(0xffffffffu, s1, o);
        s2 += __shfl_xor_sync(0xffffffffu, s2, o);
    }
    int warp = tid >> 5;
    if ((tid & 31) == 0) { wsum[warp] = s1; wsq[warp] = s2; }
    __syncthreads();
    int w0 = p << 1;
    float mu  = (wsum[w0] + wsum[w0+1]) * 0.015625f;
    float var = (wsq [w0] + wsq [w0+1]) * 0.015625f - mu * mu;
    g_hn[token*64 + c] = (r - mu) * rsqrtf(var + 1e-5f) * ln_g[c] + ln_b[c];
}

// ============================================================
// K2: in_proj GEMM  [B*L,64] x [256,64]^T -> xm [.,128], z [.,128]
// 16 tokens per 256-thread block; thread = output dim d.
// ============================================================
__global__ void k_inproj(const float* __restrict__ W) {
    __shared__ float hs[16][64];
    int tid = threadIdx.x;
    int t0 = blockIdx.x * 16;
    for (int i = tid; i < 16*64; i += 256)
        hs[i >> 6][i & 63] = g_hn[t0*64 + i];
    __syncthreads();
    const float* wr = W + tid * 64;
    float acc[16];
    #pragma unroll
    for (int r = 0; r < 16; r++) acc[r] = 0.f;
    #pragma unroll
    for (int k = 0; k < 64; k++) {
        float wv = wr[k];
        #pragma unroll
        for (int r = 0; r < 16; r++) acc[r] += hs[r][k] * wv;
    }
    if (tid < 128) {
        #pragma unroll
        for (int r = 0; r < 16; r++) g_xm[(t0 + r)*DD + tid] = acc[r];
    } else {
        #pragma unroll
        for (int r = 0; r < 16; r++) g_z[(t0 + r)*DD + (tid - 128)] = acc[r];
    }
}

// ============================================================
// K3: causal depthwise conv1d(k=4) + SiLU -> xc ; x_proj -> (dt_low,B,C) ;
//     dt = softplus(dt_low @ dt_proj^T + bias).  2 tokens / 256-thread block.
// ============================================================
__global__ void k_conv1d(const float* __restrict__ cw, const float* __restrict__ cb,
                         const float* __restrict__ xpw, const float* __restrict__ dpw,
                         const float* __restrict__ dpb) {
    __shared__ float xcs[2][128];
    __shared__ float dbcs[2][36];
    int tid = threadIdx.x;
    int tok = tid >> 7, d = tid & 127;
    int token = blockIdx.x * 2 + tok;
    int b = token >> 12, l = token & 4095;
    float acc = cb[d];
    #pragma unroll
    for (int j = 0; j < 4; j++) {
        int lj = l - 3 + j;
        if (lj >= 0) acc += cw[d*4 + j] * g_xm[(((b << 12) + lj)*DD) + d];
    }
    float xcv = acc / (1.f + __expf(-acc));          // SiLU
    xcs[tok][d] = xcv;
    g_xc[token*DD + d] = xcv;
    __syncthreads();
    if (d < 36) {
        const float* xw = xpw + d * 128;
        float a = 0.f;
        #pragma unroll
        for (int k = 0; k < 128; k++) a += xw[k] * xcs[tok][k];
        dbcs[tok][d] = a;
    }
    __syncthreads();
    float tv = dpb[d];
    #pragma unroll
    for (int r = 0; r < 4; r++) tv += dbcs[tok][r] * dpw[d*4 + r];
    float dtv = (tv > 20.f) ? tv : log1pf(__expf(tv));   // softplus
    g_dt[token*DD + d] = dtv;
    if (d < 16)       g_Bc[token*SS + d]        = dbcs[tok][4 + d];
    else if (d < 32)  g_Cc[token*SS + (d - 16)] = dbcs[tok][4 + d];
}

// ============================================================
// K4a: scan phase 1 — per-chunk local scan (h from 0) + decay product.
// block = 512 thr = 32 d x 16 s ; grid = B*NCH*4
// ============================================================
__global__ void k_scan1(const float* __restrict__ A_log) {
    int tid = threadIdx.x;
    int bc = blockIdx.x >> 2;          // b*64 + chunk
    int dg = blockIdx.x & 3;
    int d = dg*32 + (tid >> 4);
    int s = tid & 15;
    int b = bc >> 6, chunk = bc & 63;
    float A = -expf(A_log[d*SS + s]);
    int base = (b << 12) + (chunk << 6);
    float h = 0.f, P = 1.f;
    #pragma unroll 4
    for (int t = 0; t < TCH; t++) {
        int l = base + t;
        float dtv = g_dt[l*DD + d];
        float xcv = g_xc[l*DD + d];
        float Bv  = g_Bc[l*SS + s];
        float a = __expf(dtv * A);
        h = h * a + dtv * Bv * xcv;
        P *= a;
    }
    int idx = (bc*DD + d)*SS + s;
    g_P[idx] = P;
    g_H[idx] = h;
}

// ============================================================
// K4b: scan phase 2 — sequential combine across chunks (8192 threads).
// Converts g_H from chunk end-states to chunk START-states in place.
// ============================================================
__global__ void k_scan2() {
    int gid = blockIdx.x * blockDim.x + threadIdx.x;   // 0..8191
    int b  = gid >> 11;      // 2048 = D*S per batch
    int ds = gid & 2047;
    float H = 0.f;
    for (int c = 0; c < NCH; c++) {
        int idx = (b*NCH + c)*2048 + ds;
        float Hs = H;
        H = g_P[idx] * H + g_H[idx];
        g_H[idx] = Hs;             // start state for chunk c
    }
}

// ============================================================
// K4c: scan phase 3 — re-run chunks from corrected start states, emit y.
// ============================================================
__global__ void k_scan3(const float* __restrict__ A_log) {
    int tid = threadIdx.x;
    int bc = blockIdx.x >> 2;
    int dg = blockIdx.x & 3;
    int d = dg*32 + (tid >> 4);
    int s = tid & 15;
    int b = bc >> 6, chunk = bc & 63;
    float A = -expf(A_log[d*SS + s]);
    float h = g_H[(bc*DD + d)*SS + s];
    int base = (b << 12) + (chunk << 6);
    #pragma unroll 4
    for (int t = 0; t < TCH; t++) {
        int l = base + t;
        float dtv = g_dt[l*DD + d];
        float xcv = g_xc[l*DD + d];
        float Bv  = g_Bc[l*SS + s];
        float Cv  = g_Cc[l*SS + s];
        float a = __expf(dtv * A);
        h = h * a + dtv * Bv * xcv;
        float pc = h * Cv;
        pc += __shfl_xor_sync(0xffffffffu, pc, 1);
        pc += __shfl_xor_sync(0xffffffffu, pc, 2);
        pc += __shfl_xor_sync(0xffffffffu, pc, 4);
        pc += __shfl_xor_sync(0xffffffffu, pc, 8);
        if (s == 0) g_y[l*DD + d] = pc;
    }
}

// ============================================================
// K5: gating epilogue + out_proj GEMM + residual, write NCHW output.
// 2 tokens per 256-thread block.
// ============================================================
__global__ void k_out(const float* __restrict__ Dp, const float* __restrict__ Wout,
                      float* __restrict__ out) {
    __shared__ float gs[2][128];
    int tid = threadIdx.x;
    int tok = tid >> 7, d = tid & 127;
    int token = blockIdx.x * 2 + tok;
    int b = token >> 12, l = token & 4095;
    float yv  = g_y [token*DD + d];
    float xcv = g_xc[token*DD + d];
    float zv  = g_z [token*DD + d];
    float gval = (yv + xcv * Dp[d]) * (zv / (1.f + __expf(-zv)));
    gs[tok][d] = gval;
    __syncthreads();
    if (d < 64) {
        const float* wr = Wout + d * 128;       // row c = d
        float a = 0.f;
        #pragma unroll
        for (int k = 0; k < 128; k++) a += wr[k] * gs[tok][k];
        out[((b*64 + d) << 12) + l] = a + g_seq[token*64 + d];
    }
}

// ============================================================
extern "C" void kernel_launch(void* const* d_in, const int* in_sizes, int n_in,
                              void* d_out, int out_size) {
    const float* x        = (const float*)d_in[0];
    const float* dwh_w    = (const float*)d_in[1];
    const float* dwh_b    = (const float*)d_in[2];
    const float* dww_w    = (const float*)d_in[3];
    const float* dww_b    = (const float*)d_in[4];
    const float* conv_w   = (const float*)d_in[5];
    const float* conv_b   = (const float*)d_in[6];
    const float* bn_g     = (const float*)d_in[7];
    const float* bn_b     = (const float*)d_in[8];
    const float* bn_m     = (const float*)d_in[9];
    const float* bn_v     = (const float*)d_in[10];
    const float* ln_g     = (const float*)d_in[11];
    const float* ln_b     = (const float*)d_in[12];
    const float* in_proj  = (const float*)d_in[13];
    const float* convd_w  = (const float*)d_in[14];
    const float* convd_b  = (const float*)d_in[15];
    const float* x_proj   = (const float*)d_in[16];
    const float* dt_proj_w= (const float*)d_in[17];
    const float* dt_proj_b= (const float*)d_in[18];
    const float* A_log    = (const float*)d_in[19];
    const float* Dp       = (const float*)d_in[20];
    const float* out_proj = (const float*)d_in[21];
    float* out = (float*)d_out;

    k_axial  <<<BB*CC*16, 256>>>(x, dwh_w, dwh_b, dww_w, dww_b);
    k_conv1x1<<<BB*LL/4,  256>>>(conv_w, conv_b, bn_g, bn_b, bn_m, bn_v, ln_g, ln_b);
    k_inproj <<<BB*LL/16, 256>>>(in_proj);
    k_conv1d <<<BB*LL/2,  256>>>(convd_w, convd_b, x_proj, dt_proj_w, dt_proj_b);
    k_scan1  <<<BB*NCH*4, 512>>>(A_log);
    k_scan2  <<<32,       256>>>();
    k_scan3  <<<BB*NCH*4, 512>>>(A_log);
    k_out    <<<BB*LL/2,  256>>>(Dp, out_proj, out);
}

// round 2
// speedup vs baseline: 6.2368x; 6.2368x over previous
#include <cuda_runtime.h>
#include <math.h>

#define BB 4
#define CC 64
#define HHH 64
#define WWW 64
#define LL 4096
#define DD 128
#define SS 16
#define NCH 64
#define TCH 64

// ---- scratch ----
__device__ float g_t  [BB*LL*CC];
__device__ float g_seq[BB*LL*CC];
__device__ float g_hn [BB*LL*CC];
__device__ float g_xm [BB*LL*DD];
__device__ float g_z  [BB*LL*DD];
__device__ float g_xc [BB*LL*DD];
__device__ float g_dt [BB*LL*DD];
__device__ float g_Bc [BB*LL*SS];
__device__ float g_Cc [BB*LL*SS];
__device__ float g_y  [BB*LL*DD];
__device__ float g_P  [BB*NCH*DD*SS];
__device__ float g_H  [BB*NCH*DD*SS];
__device__ float4 g_Win4 [16*256];   // [k4][n] : in_proj[n*64 + 4k4 ..]
__device__ float4 g_Wout4[32*64];    // [k4][c] : out_proj[c*128 + 4k4 ..]

// ============================================================
// K0: weight re-layout (tiny, one-time per launch)
// ============================================================
__global__ void k_prep(const float* __restrict__ in_proj, const float* __restrict__ out_proj) {
    int i = blockIdx.x * 256 + threadIdx.x;   // 4096 threads
    {
        int k4 = i >> 8, n = i & 255;
        const float* p = in_proj + n*64 + k4*4;
        g_Win4[i] = make_float4(p[0], p[1], p[2], p[3]);
    }
    if (i < 2048) {
        int k4 = i >> 6, c = i & 63;
        const float* p = out_proj + c*128 + k4*4;
        g_Wout4[i] = make_float4(p[0], p[1], p[2], p[3]);
    }
}

// ============================================================
// K1a: axial depthwise convs + residual + biases (NCHW read, [b,l,c] write)
// ============================================================
__global__ void k_axial(const float* __restrict__ x,
                        const float* __restrict__ whw, const float* __restrict__ whb,
                        const float* __restrict__ www, const float* __restrict__ wwb) {
    int bidx = blockIdx.x;            // B*C*16 = 4096
    int b  = bidx >> 10;
    int c  = (bidx >> 4) & 63;
    int hg = bidx & 15;
    int h  = (hg << 2) + (threadIdx.x >> 6);
    int w  = threadIdx.x & 63;
    const float* xb = x + ((b*CC + c)*HHH)*WWW;
    float x0  = xb[h*WWW + w];
    float xhm = (h > 0)       ? xb[(h-1)*WWW + w] : 0.f;
    float xhp = (h < HHH-1)   ? xb[(h+1)*WWW + w] : 0.f;
    float xwm = (w > 0)       ? xb[h*WWW + w - 1] : 0.f;
    float xwp = (w < WWW-1)   ? xb[h*WWW + w + 1] : 0.f;
    float t = x0
        + whw[c*3+0]*xhm + whw[c*3+1]*x0 + whw[c*3+2]*xhp + whb[c]
        + www[c*3+0]*xwm + www[c*3+1]*x0 + www[c*3+2]*xwp + wwb[c];
    g_t[((b*LL) + h*WWW + w)*CC + c] = t;
}

// ============================================================
// K1b: 1x1 conv + BN + ReLU + LayerNorm.  16 tokens / 256 threads.
// ============================================================
__global__ void k_conv1x1(const float* __restrict__ conv_w, const float* __restrict__ conv_b,
                          const float* __restrict__ bn_g, const float* __restrict__ bn_b,
                          const float* __restrict__ bn_m, const float* __restrict__ bn_v,
                          const float* __restrict__ ln_g, const float* __restrict__ ln_b) {
    __shared__ float w_sh[64*65];                  // [in][out] padded
    __shared__ __align__(16) float tsh[16*64];     // [token][in]
    __shared__ float wsum[32], wsq[32];            // [j][warp]
    int tid = threadIdx.x;
    int t0 = blockIdx.x * 16;
    for (int i = tid; i < 4096; i += 256) {        // coalesced read, padded write
        int outc = i >> 6, in = i & 63;
        w_sh[in*65 + outc] = conv_w[i];
    }
    for (int i = tid; i < 1024; i += 256) tsh[i] = g_t[t0*64 + i];
    __syncthreads();

    int c = tid & 63, tg = tid >> 6;               // 4 tokens per thread
    float cbv = conv_b[c];
    float acc[4] = {cbv, cbv, cbv, cbv};
    #pragma unroll
    for (int k4 = 0; k4 < 16; k4++) {
        float wv0 = w_sh[(k4*4+0)*65 + c];
        float wv1 = w_sh[(k4*4+1)*65 + c];
        float wv2 = w_sh[(k4*4+2)*65 + c];
        float wv3 = w_sh[(k4*4+3)*65 + c];
        #pragma unroll
        for (int j = 0; j < 4; j++) {
            float4 t4 = *(const float4*)(tsh + (tg*4+j)*64 + k4*4);
            acc[j] += t4.x*wv0 + t4.y*wv1 + t4.z*wv2 + t4.w*wv3;
        }
    }
    float bnscale = rsqrtf(bn_v[c] + 1e-5f) * bn_g[c];
    float bnm = bn_m[c], bnb = bn_b[c];
    float rr[4];
    #pragma unroll
    for (int j = 0; j < 4; j++) {
        float r = fmaxf((acc[j] - bnm) * bnscale + bnb, 0.f);
        rr[j] = r;
        g_seq[(t0 + tg*4 + j)*64 + c] = r;
    }
    int warp = tid >> 5;
    #pragma unroll
    for (int j = 0; j < 4; j++) {
        float s1 = rr[j], s2 = rr[j]*rr[j];
        #pragma unroll
        for (int o = 16; o; o >>= 1) {
            s1 += __shfl_xor_sync(0xffffffffu, s1, o);
            s2 += __shfl_xor_sync(0xffffffffu, s2, o);
        }
        if ((tid & 31) == 0) { wsum[j*8 + warp] = s1; wsq[j*8 + warp] = s2; }
    }
    __syncthreads();
    float lg = ln_g[c], lb = ln_b[c];
    #pragma unroll
    for (int j = 0; j < 4; j++) {
        float mu  = (wsum[j*8 + 2*tg] + wsum[j*8 + 2*tg+1]) * 0.015625f;
        float var = (wsq [j*8 + 2*tg] + wsq [j*8 + 2*tg+1]) * 0.015625f - mu*mu;
        g_hn[(t0 + tg*4 + j)*64 + c] = (rr[j] - mu) * rsqrtf(var + 1e-5f) * lg + lb;
    }
}

// ============================================================
// K2: in_proj GEMM. 16 tokens / 128 threads; thread handles n=tid and n=tid+128.
// ============================================================
__global__ void k_inproj() {
    __shared__ __align__(16) float hs[16*64];
    int tid = threadIdx.x;                         // 0..127
    int t0 = blockIdx.x * 16;
    for (int i = tid; i < 1024; i += 128) hs[i] = g_hn[t0*64 + i];
    __syncthreads();
    float acc0[16], acc1[16];
    #pragma unroll
    for (int r = 0; r < 16; r++) { acc0[r] = 0.f; acc1[r] = 0.f; }
    #pragma unroll
    for (int k4 = 0; k4 < 16; k4++) {
        float4 w0 = g_Win4[k4*256 + tid];
        float4 w1 = g_Win4[k4*256 + tid + 128];
        #pragma unroll
        for (int r = 0; r < 16; r++) {
            float4 h4 = *(const float4*)(hs + r*64 + k4*4);
            acc0[r] += h4.x*w0.x + h4.y*w0.y + h4.z*w0.z + h4.w*w0.w;
            acc1[r] += h4.x*w1.x + h4.y*w1.y + h4.z*w1.z + h4.w*w1.w;
        }
    }
    #pragma unroll
    for (int r = 0; r < 16; r++) {
        g_xm[(t0 + r)*DD + tid] = acc0[r];
        g_z [(t0 + r)*DD + tid] = acc1[r];
    }
}

// ============================================================
// K3: causal dw-conv1d(k=4)+SiLU, x_proj, dt/B/C.  32 tokens / 256 threads.
// ============================================================
__global__ void k_conv1d(const float* __restrict__ xpw,
                         const float* __restrict__ cw, const float* __restrict__ cb,
                         const float* __restrict__ dpw, const float* __restrict__ dpb) {
    __shared__ __align__(16) float xpw_sh[36*128];   // [e][k]
    __shared__ __align__(16) float xc_sh[32*132];    // [token][k] pad 132
    __shared__ float dbc_sh[32*38];                  // [token][e]
    __shared__ __align__(16) float cw_sh[512];
    __shared__ float cb_sh[128];
    __shared__ __align__(16) float dpw_sh[512];
    __shared__ float dpb_sh[128];
    int tid = threadIdx.x;
    int t0 = blockIdx.x * 32;
    for (int i = tid; i < 4608; i += 256) xpw_sh[i] = xpw[i];
    for (int i = tid; i < 512; i += 256) { cw_sh[i] = cw[i]; dpw_sh[i] = dpw[i]; }
    if (tid < 128) { cb_sh[tid] = cb[tid]; dpb_sh[tid] = dpb[tid]; }
    __syncthreads();

    // depthwise causal conv + SiLU
    for (int i = tid; i < 32*128; i += 256) {
        int tl = i >> 7, d = i & 127;
        int token = t0 + tl;
        int l = token & 4095;
        float acc = cb_sh[d];
        #pragma unroll
        for (int j = 0; j < 4; j++) {
            int lj = l - 3 + j;
            if (lj >= 0) acc += cw_sh[d*4+j] * g_xm[(token - 3 + j)*DD + d];
        }
        float v = acc / (1.f + __expf(-acc));
        xc_sh[tl*132 + d] = v;
        g_xc[token*DD + d] = v;
    }
    __syncthreads();

    // x_proj: 32 tokens x 36 outputs
    {
        int tl = tid & 31, eb = tid >> 5;            // warp-uniform eb
        float acc[5] = {0.f, 0.f, 0.f, 0.f, 0.f};
        const float4* xc4 = (const float4*)(xc_sh + tl*132);
        #pragma unroll
        for (int k4 = 0; k4 < 32; k4++) {
            float4 xv = xc4[k4];
            #pragma unroll
            for (int ii = 0; ii < 5; ii++) {
                int e = eb + ii*8;
                if (e < 36) {
                    float4 wv = *(const float4*)(xpw_sh + e*128 + k4*4);
                    acc[ii] += xv.x*wv.x + xv.y*wv.y + xv.z*wv.z + xv.w*wv.w;
                }
            }
        }
        #pragma unroll
        for (int ii = 0; ii < 5; ii++) {
            int e = eb + ii*8;
            if (e < 36) dbc_sh[tl*38 + e] = acc[ii];
        }
    }
    __syncthreads();

    // dt = softplus(dbc[0:4] @ dpw^T + dpb)
    for (int i = tid; i < 32*128; i += 256) {
        int tl = i >> 7, d = i & 127;
        float4 dp4 = *(const float4*)(dpw_sh + d*4);
        const float* db = dbc_sh + tl*38;
        float tv = dpb_sh[d] + db[0]*dp4.x + db[1]*dp4.y + db[2]*dp4.z + db[3]*dp4.w;
        float dtv = (tv > 20.f) ? tv : log1pf(__expf(tv));
        g_dt[(t0 + tl)*DD + d] = dtv;
    }
    for (int i = tid; i < 512; i += 256) {
        int tl = i >> 4, s = i & 15;
        g_Bc[(t0 + tl)*SS + s] = dbc_sh[tl*38 + 4 + s];
        g_Cc[(t0 + tl)*SS + s] = dbc_sh[tl*38 + 20 + s];
    }
}

// ============================================================
// K4a: scan phase 1 — local chunk scan + decay product. 512 thr, grid B*NCH*4.
// ============================================================
__global__ void k_scan1(const float* __restrict__ A_log) {
    __shared__ float dt_sh[64*32], xcs[64*32], Bs[64*16];
    int tid = threadIdx.x;
    int bc = blockIdx.x >> 2;
    int dg = blockIdx.x & 3;
    int dl = tid >> 4, s = tid & 15;
    int d = dg*32 + dl;
    int b = bc >> 6, chunk = bc & 63;
    int base = (b << 12) + (chunk << 6);
    for (int i = tid; i < 2048; i += 512) {
        int t = i >> 5, dj = i & 31;
        dt_sh[i] = g_dt[(base + t)*DD + dg*32 + dj];
        xcs[i]   = g_xc[(base + t)*DD + dg*32 + dj];
    }
    for (int i = tid; i < 1024; i += 512) Bs[i] = g_Bc[base*SS + i];
    float A = -__expf(A_log[d*SS + s]);
    __syncthreads();
    float h = 0.f, P = 1.f;
    #pragma unroll 8
    for (int t = 0; t < TCH; t++) {
        float dtv = dt_sh[t*32 + dl];
        float a = __expf(dtv * A);
        h = h * a + dtv * Bs[t*16 + s] * xcs[t*32 + dl];
        P *= a;
    }
    int idx = (bc*DD + d)*SS + s;
    g_P[idx] = P;
    g_H[idx] = h;
}

// ============================================================
// K4b: scan phase 2 — combine across chunks (end-states -> start-states).
// ============================================================
__global__ void k_scan2() {
    int gid = blockIdx.x * blockDim.x + threadIdx.x;   // 0..8191
    int b  = gid >> 11;
    int ds = gid & 2047;
    float H = 0.f;
    #pragma unroll 4
    for (int c = 0; c < NCH; c++) {
        int idx = (b*NCH + c)*2048 + ds;
        float Hs = H;
        H = g_P[idx] * H + g_H[idx];
        g_H[idx] = Hs;
    }
}

// ============================================================
// K4c: scan phase 3 — re-run from corrected start states, emit y via shared.
// ============================================================
__global__ void k_scan3(const float* __restrict__ A_log) {
    __shared__ float dt_sh[64*32], xcs[64*32], Bs[64*16], Cs[64*16];
    __shared__ float ysh[64*33];
    int tid = threadIdx.x;
    int bc = blockIdx.x >> 2;
    int dg = blockIdx.x & 3;
    int dl = tid >> 4, s = tid & 15;
    int d = dg*32 + dl;
    int b = bc >> 6, chunk = bc & 63;
    int base = (b << 12) + (chunk << 6);
    for (int i = tid; i < 2048; i += 512) {
        int t = i >> 5, dj = i & 31;
        dt_sh[i] = g_dt[(base + t)*DD + dg*32 + dj];
        xcs[i]   = g_xc[(base + t)*DD + dg*32 + dj];
    }
    for (int i = tid; i < 1024; i += 512) {
        Bs[i] = g_Bc[base*SS + i];
        Cs[i] = g_Cc[base*SS + i];
    }
    float A = -__expf(A_log[d*SS + s]);
    float h = g_H[(bc*DD + d)*SS + s];
    __syncthreads();
    #pragma unroll 4
    for (int t = 0; t < TCH; t++) {
        float dtv = dt_sh[t*32 + dl];
        float a = __expf(dtv * A);
        h = h * a + dtv * Bs[t*16 + s] * xcs[t*32 + dl];
        float pc = h * Cs[t*16 + s];
        pc += __shfl_xor_sync(0xffffffffu, pc, 1);
        pc += __shfl_xor_sync(0xffffffffu, pc, 2);
        pc += __shfl_xor_sync(0xffffffffu, pc, 4);
        pc += __shfl_xor_sync(0xffffffffu, pc, 8);
        if (s == 0) ysh[t*33 + dl] = pc;
    }
    __syncthreads();
    for (int i = tid; i < 2048; i += 512) {
        int t = i >> 5, dj = i & 31;
        g_y[(base + t)*DD + dg*32 + dj] = ysh[t*33 + dj];
    }
}

// ============================================================
// K5: gating + out_proj + residual, write NCHW. 16 tokens / 256 threads.
// ============================================================
__global__ void k_out(const float* __restrict__ Dp, float* __restrict__ out) {
    __shared__ __align__(16) float gs[16*128];
    __shared__ float res[64*17];
    int tid = threadIdx.x;
    int t0 = blockIdx.x * 16;
    for (int i = tid; i < 2048; i += 256) {
        int tl = i >> 7, d = i & 127;
        int token = t0 + tl;
        float yv  = g_y [token*DD + d];
        float xcv = g_xc[token*DD + d];
        float zv  = g_z [token*DD + d];
        gs[i] = (yv + xcv * Dp[d]) * (zv / (1.f + __expf(-zv)));
    }
    __syncthreads();
    int c = tid & 63, tg = tid >> 6;            // 4 tokens per thread
    float acc[4] = {0.f, 0.f, 0.f, 0.f};
    #pragma unroll
    for (int k4 = 0; k4 < 32; k4++) {
        float4 w4 = g_Wout4[k4*64 + c];
        #pragma unroll
        for (int j = 0; j < 4; j++) {
            float4 g4 = *(const float4*)(gs + (tg*4+j)*128 + k4*4);
            acc[j] += g4.x*w4.x + g4.y*w4.y + g4.z*w4.z + g4.w*w4.w;
        }
    }
    #pragma unroll
    for (int j = 0; j < 4; j++)
        res[c*17 + tg*4 + j] = acc[j] + g_seq[(t0 + tg*4 + j)*64 + c];
    __syncthreads();
    int b = t0 >> 12, l0 = t0 & 4095;
    for (int i = tid; i < 1024; i += 256) {
        int cc = i >> 4, t = i & 15;
        out[((b*64 + cc) << 12) + l0 + t] = res[cc*17 + t];
    }
}

// ============================================================
extern "C" void kernel_launch(void* const* d_in, const int* in_sizes, int n_in,
                              void* d_out, int out_size) {
    const float* x        = (const float*)d_in[0];
    const float* dwh_w    = (const float*)d_in[1];
    const float* dwh_b    = (const float*)d_in[2];
    const float* dww_w    = (const float*)d_in[3];
    const float* dww_b    = (const float*)d_in[4];
    const float* conv_w   = (const float*)d_in[5];
    const float* conv_b   = (const float*)d_in[6];
    const float* bn_g     = (const float*)d_in[7];
    const float* bn_b     = (const float*)d_in[8];
    const float* bn_m     = (const float*)d_in[9];
    const float* bn_v     = (const float*)d_in[10];
    const float* ln_g     = (const float*)d_in[11];
    const float* ln_b     = (const float*)d_in[12];
    const float* in_proj  = (const float*)d_in[13];
    const float* convd_w  = (const float*)d_in[14];
    const float* convd_b  = (const float*)d_in[15];
    const float* x_proj   = (const float*)d_in[16];
    const float* dt_proj_w= (const float*)d_in[17];
    const float* dt_proj_b= (const float*)d_in[18];
    const float* A_log    = (const float*)d_in[19];
    const float* Dp       = (const float*)d_in[20];
    const float* out_proj = (const float*)d_in[21];
    float* out = (float*)d_out;

    k_prep   <<<16,       256>>>(in_proj, out_proj);
    k_axial  <<<BB*CC*16, 256>>>(x, dwh_w, dwh_b, dww_w, dww_b);
    k_conv1x1<<<BB*LL/16, 256>>>(conv_w, conv_b, bn_g, bn_b, bn_m, bn_v, ln_g, ln_b);
    k_inproj <<<BB*LL/16, 128>>>();
    k_conv1d <<<BB*LL/32, 256>>>(x_proj, convd_w, convd_b, dt_proj_w, dt_proj_b);
    k_scan1  <<<BB*NCH*4, 512>>>(A_log);
    k_scan2  <<<32,       256>>>();
    k_scan3  <<<BB*NCH*4, 512>>>(A_log);
    k_out    <<<BB*LL/16, 256>>>(Dp, out);
}

// round 5
// speedup vs baseline: 6.3142x; 1.0124x over previous
#include <cuda_runtime.h>
#include <math.h>

#define BB 4
#define CC 64
#define HHH 64
#define WWW 64
#define LL 4096
#define DD 128
#define SS 16
#define NCH 64
#define TCH 64

// ---- scratch ----
__device__ float g_seq[BB*LL*CC];
__device__ float g_xm [BB*LL*DD];
__device__ float g_z  [BB*LL*DD];
__device__ float g_xc [BB*LL*DD];
__device__ float g_dt [BB*LL*DD];
__device__ float g_Bc [BB*LL*SS];
__device__ float g_Cc [BB*LL*SS];
__device__ float g_y  [BB*LL*DD];
__device__ float g_P  [BB*NCH*DD*SS];
__device__ float g_H  [BB*NCH*DD*SS];
__device__ float4 g_Win4 [16*256];   // [k4][n] : in_proj[n*64 + 4k4 ..]
__device__ float4 g_Wout4[32*64];    // [k4][c] : out_proj[c*128 + 4k4 ..]

// packed fp32x2 FMA (sm_100+; PTX-only encoding)
__device__ __forceinline__ float2 ffma2(float2 d, float2 a, float2 b) {
    unsigned long long dd = *(unsigned long long*)&d;
    unsigned long long aa = *(unsigned long long*)&a;
    unsigned long long bb = *(unsigned long long*)&b;
    asm("fma.rn.f32x2 %0, %1, %2, %0;" : "+l"(dd) : "l"(aa), "l"(bb));
    return *(float2*)&dd;
}
__device__ __forceinline__ float ex2f(float x) {
    float r; asm("ex2.approx.f32 %0, %1;" : "=f"(r) : "f"(x)); return r;
}

// ============================================================
// K0: weight re-layout (tiny)
// ============================================================
__global__ void k_prep(const float* __restrict__ in_proj, const float* __restrict__ out_proj) {
    int i = blockIdx.x * 256 + threadIdx.x;   // 4096 threads
    {
        int k4 = i >> 8, n = i & 255;
        const float* p = in_proj + n*64 + k4*4;
        g_Win4[i] = make_float4(p[0], p[1], p[2], p[3]);
    }
    if (i < 2048) {
        int k4 = i >> 6, c = i & 63;
        const float* p = out_proj + c*128 + k4*4;
        g_Wout4[i] = make_float4(p[0], p[1], p[2], p[3]);
    }
}

// ============================================================
// K1: FUSED front: axial dw-convs + 1x1 conv + BN + ReLU + LN + in_proj.
// Block = 16 tokens (16 consecutive w of one row h), 256 threads.
// ============================================================
__global__ void k_front(const float* __restrict__ x,
                        const float* __restrict__ whw, const float* __restrict__ whb,
                        const float* __restrict__ www, const float* __restrict__ wwb,
                        const float* __restrict__ conv_w, const float* __restrict__ conv_b,
                        const float* __restrict__ bn_g, const float* __restrict__ bn_b,
                        const float* __restrict__ bn_m, const float* __restrict__ bn_v,
                        const float* __restrict__ ln_g, const float* __restrict__ ln_b) {
    __shared__ float xs[64*55];                    // [c][3*18] pad 55 (halo tile)
    __shared__ float w_sh[64*65];                  // 1x1 weights [in][out] padded
    __shared__ __align__(16) float tsh[16*64];     // axial output [token][c]
    __shared__ __align__(16) float hs[16*64];      // layernorm out [token][c]
    __shared__ float wsum[32], wsq[32];
    int tid = threadIdx.x;
    int t0 = blockIdx.x * 16;
    int b = t0 >> 12, l0 = t0 & 4095;
    int h = l0 >> 6, w0 = l0 & 63;

    // stage halo tile: 64 c x rows (h-1,h,h+1) x w (w0-1 .. w0+16)
    for (int i = tid; i < 64*54; i += 256) {
        int c = i / 54, rem = i % 54;
        int r = rem / 18, ww = rem % 18;
        int hr = h - 1 + r;
        int wr = w0 - 1 + ww;
        float v = 0.f;
        if (hr >= 0 && hr < 64 && wr >= 0 && wr < 64)
            v = x[(((b*64 + c)*64 + hr) << 6) + wr];
        xs[c*55 + rem] = v;
    }
    // stage 1x1 conv weights (coalesced read, transposed padded write)
    for (int i = tid; i < 4096; i += 256) {
        int outc = i >> 6, in = i & 63;
        w_sh[in*65 + outc] = conv_w[i];
    }
    __syncthreads();

    int c = tid & 63, tg = tid >> 6;
    // axial depthwise stencil for 4 tokens of channel c
    {
        float a0 = whw[c*3+0], a1 = whw[c*3+1], a2 = whw[c*3+2];
        float b0 = www[c*3+0], b1 = www[c*3+1], b2 = www[c*3+2];
        float bias = whb[c] + wwb[c];
        const float* xr = xs + c*55;
        #pragma unroll
        for (int j = 0; j < 4; j++) {
            int wl = tg*4 + j;          // 0..15
            int ww = wl + 1;            // center in halo coords
            float x0  = xr[18 + ww];
            float t = x0 + bias
                + a0*xr[ww] + a1*x0 + a2*xr[36 + ww]
                + b0*xr[18 + ww - 1] + b1*x0 + b2*xr[18 + ww + 1];
            tsh[wl*64 + c] = t;
        }
    }
    __syncthreads();

    // 1x1 conv (f32x2-packed reduction) + BN + ReLU
    float cbv = conv_b[c];
    float2 acc2[4];
    #pragma unroll
    for (int j = 0; j < 4; j++) acc2[j] = make_float2(cbv, 0.f);
    #pragma unroll
    for (int k4 = 0; k4 < 16; k4++) {
        float2 wA = make_float2(w_sh[(k4*4+0)*65 + c], w_sh[(k4*4+1)*65 + c]);
        float2 wB = make_float2(w_sh[(k4*4+2)*65 + c], w_sh[(k4*4+3)*65 + c]);
        #pragma unroll
        for (int j = 0; j < 4; j++) {
            float4 t4 = *(const float4*)(tsh + (tg*4+j)*64 + k4*4);
            acc2[j] = ffma2(acc2[j], make_float2(t4.x, t4.y), wA);
            acc2[j] = ffma2(acc2[j], make_float2(t4.z, t4.w), wB);
        }
    }
    float bnscale = rsqrtf(bn_v[c] + 1e-5f) * bn_g[c];
    float bnm = bn_m[c], bnb = bn_b[c];
    float rr[4];
    #pragma unroll
    for (int j = 0; j < 4; j++) {
        float r = fmaxf((acc2[j].x + acc2[j].y - bnm) * bnscale + bnb, 0.f);
        rr[j] = r;
        g_seq[(t0 + tg*4 + j)*64 + c] = r;
    }
    // LayerNorm over c (2 warps per token group)
    int warp = tid >> 5;
    #pragma unroll
    for (int j = 0; j < 4; j++) {
        float s1 = rr[j], s2 = rr[j]*rr[j];
        #pragma unroll
        for (int o = 16; o; o >>= 1) {
            s1 += __shfl_xor_sync(0xffffffffu, s1, o);
            s2 += __shfl_xor_sync(0xffffffffu, s2, o);
        }
        if ((tid & 31) == 0) { wsum[j*8 + warp] = s1; wsq[j*8 + warp] = s2; }
    }
    __syncthreads();
    float lg = ln_g[c], lb = ln_b[c];
    #pragma unroll
    for (int j = 0; j < 4; j++) {
        float mu  = (wsum[j*8 + 2*tg] + wsum[j*8 + 2*tg+1]) * 0.015625f;
        float var = (wsq [j*8 + 2*tg] + wsq [j*8 + 2*tg+1]) * 0.015625f - mu*mu;
        hs[(tg*4 + j)*64 + c] = (rr[j] - mu) * rsqrtf(var + 1e-5f) * lg + lb;
    }
    __syncthreads();

    // in_proj: thread = output n (0..255), 16 tokens, f32x2-packed reduction
    int n = tid;
    float2 in2[16];
    #pragma unroll
    for (int r = 0; r < 16; r++) in2[r] = make_float2(0.f, 0.f);
    #pragma unroll
    for (int k4 = 0; k4 < 16; k4++) {
        float4 w4 = g_Win4[k4*256 + n];
        float2 wA = make_float2(w4.x, w4.y);
        float2 wB = make_float2(w4.z, w4.w);
        #pragma unroll
        for (int r = 0; r < 16; r++) {
            float4 h4 = *(const float4*)(hs + r*64 + k4*4);
            in2[r] = ffma2(in2[r], make_float2(h4.x, h4.y), wA);
            in2[r] = ffma2(in2[r], make_float2(h4.z, h4.w), wB);
        }
    }
    if (n < 128) {
        #pragma unroll
        for (int r = 0; r < 16; r++) g_xm[(t0 + r)*DD + n] = in2[r].x + in2[r].y;
    } else {
        #pragma unroll
        for (int r = 0; r < 16; r++) g_z[(t0 + r)*DD + (n - 128)] = in2[r].x + in2[r].y;
    }
}

// ============================================================
// K3: causal dw-conv1d(k=4)+SiLU, x_proj, dt/B/C.  32 tokens / 256 threads.
// ============================================================
__global__ void k_conv1d(const float* __restrict__ xpw,
                         const float* __restrict__ cw, const float* __restrict__ cb,
                         const float* __restrict__ dpw, const float* __restrict__ dpb) {
    __shared__ __align__(16) float xpw_sh[36*128];   // [e][k]
    __shared__ __align__(16) float xc_sh[32*132];    // [token][k] pad 132
    __shared__ float dbc_sh[32*38];                  // [token][e]
    __shared__ __align__(16) float cw_sh[512];
    __shared__ float cb_sh[128];
    __shared__ __align__(16) float dpw_sh[512];
    __shared__ float dpb_sh[128];
    int tid = threadIdx.x;
    int t0 = blockIdx.x * 32;
    for (int i = tid; i < 4608; i += 256) xpw_sh[i] = xpw[i];
    for (int i = tid; i < 512; i += 256) { cw_sh[i] = cw[i]; dpw_sh[i] = dpw[i]; }
    if (tid < 128) { cb_sh[tid] = cb[tid]; dpb_sh[tid] = dpb[tid]; }
    __syncthreads();

    // depthwise causal conv + SiLU
    for (int i = tid; i < 32*128; i += 256) {
        int tl = i >> 7, d = i & 127;
        int token = t0 + tl;
        int l = token & 4095;
        float acc = cb_sh[d];
        #pragma unroll
        for (int j = 0; j < 4; j++) {
            int lj = l - 3 + j;
            if (lj >= 0) acc += cw_sh[d*4+j] * g_xm[(token - 3 + j)*DD + d];
        }
        float v = acc / (1.f + __expf(-acc));
        xc_sh[tl*132 + d] = v;
        g_xc[token*DD + d] = v;
    }
    __syncthreads();

    // x_proj: 32 tokens x 36 outputs (f32x2-packed reduction)
    {
        int tl = tid & 31, eb = tid >> 5;
        float2 acc[5];
        #pragma unroll
        for (int ii = 0; ii < 5; ii++) acc[ii] = make_float2(0.f, 0.f);
        const float4* xc4 = (const float4*)(xc_sh + tl*132);
        #pragma unroll
        for (int k4 = 0; k4 < 32; k4++) {
            float4 xv = xc4[k4];
            float2 xA = make_float2(xv.x, xv.y);
            float2 xB = make_float2(xv.z, xv.w);
            #pragma unroll
            for (int ii = 0; ii < 5; ii++) {
                int e = eb + ii*8;
                if (e < 36) {
                    float4 wv = *(const float4*)(xpw_sh + e*128 + k4*4);
                    acc[ii] = ffma2(acc[ii], xA, make_float2(wv.x, wv.y));
                    acc[ii] = ffma2(acc[ii], xB, make_float2(wv.z, wv.w));
                }
            }
        }
        #pragma unroll
        for (int ii = 0; ii < 5; ii++) {
            int e = eb + ii*8;
            if (e < 36) dbc_sh[tl*38 + e] = acc[ii].x + acc[ii].y;
        }
    }
    __syncthreads();

    // dt = softplus(dbc[0:4] @ dpw^T + dpb)
    for (int i = tid; i < 32*128; i += 256) {
        int tl = i >> 7, d = i & 127;
        float4 dp4 = *(const float4*)(dpw_sh + d*4);
        const float* db = dbc_sh + tl*38;
        float tv = dpb_sh[d] + db[0]*dp4.x + db[1]*dp4.y + db[2]*dp4.z + db[3]*dp4.w;
        float dtv = (tv > 20.f) ? tv : log1pf(__expf(tv));
        g_dt[(t0 + tl)*DD + d] = dtv;
    }
    for (int i = tid; i < 512; i += 256) {
        int tl = i >> 4, s = i & 15;
        g_Bc[(t0 + tl)*SS + s] = dbc_sh[tl*38 + 4 + s];
        g_Cc[(t0 + tl)*SS + s] = dbc_sh[tl*38 + 20 + s];
    }
}

// ============================================================
// K4a: scan phase 1 — local chunk scan + decay product. 512 thr.
// ============================================================
__global__ void k_scan1(const float* __restrict__ A_log) {
    __shared__ float dt_sh[64*32], xcs[64*32], Bs[64*16];
    int tid = threadIdx.x;
    int bc = blockIdx.x >> 2;
    int dg = blockIdx.x & 3;
    int dl = tid >> 4, s = tid & 15;
    int d = dg*32 + dl;
    int b = bc >> 6, chunk = bc & 63;
    int base = (b << 12) + (chunk << 6);
    for (int i = tid; i < 2048; i += 512) {
        int t = i >> 5, dj = i & 31;
        dt_sh[i] = g_dt[(base + t)*DD + dg*32 + dj];
        xcs[i]   = g_xc[(base + t)*DD + dg*32 + dj];
    }
    for (int i = tid; i < 1024; i += 512) Bs[i] = g_Bc[base*SS + i];
    float A2 = -__expf(A_log[d*SS + s]) * 1.4426950408889634f;   // log2e folded
    __syncthreads();
    float h = 0.f, P = 1.f;
    #pragma unroll 8
    for (int t = 0; t < TCH; t++) {
        float dtv = dt_sh[t*32 + dl];
        float a = ex2f(dtv * A2);
        h = h * a + dtv * Bs[t*16 + s] * xcs[t*32 + dl];
        P *= a;
    }
    int idx = (bc*DD + d)*SS + s;
    g_P[idx] = P;
    g_H[idx] = h;
}

// ============================================================
// K4b: scan phase 2 — combine across chunks (end -> start states).
// ============================================================
__global__ void k_scan2() {
    int gid = blockIdx.x * blockDim.x + threadIdx.x;   // 0..8191
    int b  = gid >> 11;
    int ds = gid & 2047;
    float H = 0.f;
    #pragma unroll 4
    for (int c = 0; c < NCH; c++) {
        int idx = (b*NCH + c)*2048 + ds;
        float Hs = H;
        H = g_P[idx] * H + g_H[idx];
        g_H[idx] = Hs;
    }
}

// ============================================================
// K4c: scan phase 3 — re-run from corrected start states, emit y.
// ============================================================
__global__ void k_scan3(const float* __restrict__ A_log) {
    __shared__ float dt_sh[64*32], xcs[64*32], Bs[64*16], Cs[64*16];
    __shared__ float ysh[64*33];
    int tid = threadIdx.x;
    int bc = blockIdx.x >> 2;
    int dg = blockIdx.x & 3;
    int dl = tid >> 4, s = tid & 15;
    int d = dg*32 + dl;
    int b = bc >> 6, chunk = bc & 63;
    int base = (b << 12) + (chunk << 6);
    for (int i = tid; i < 2048; i += 512) {
        int t = i >> 5, dj = i & 31;
        dt_sh[i] = g_dt[(base + t)*DD + dg*32 + dj];
        xcs[i]   = g_xc[(base + t)*DD + dg*32 + dj];
    }
    for (int i = tid; i < 1024; i += 512) {
        Bs[i] = g_Bc[base*SS + i];
        Cs[i] = g_Cc[base*SS + i];
    }
    float A2 = -__expf(A_log[d*SS + s]) * 1.4426950408889634f;
    float h = g_H[(bc*DD + d)*SS + s];
    __syncthreads();
    #pragma unroll 4
    for (int t = 0; t < TCH; t++) {
        float dtv = dt_sh[t*32 + dl];
        float a = ex2f(dtv * A2);
        h = h * a + dtv * Bs[t*16 + s] * xcs[t*32 + dl];
        float pc = h * Cs[t*16 + s];
        pc += __shfl_xor_sync(0xffffffffu, pc, 1);
        pc += __shfl_xor_sync(0xffffffffu, pc, 2);
        pc += __shfl_xor_sync(0xffffffffu, pc, 4);
        pc += __shfl_xor_sync(0xffffffffu, pc, 8);
        if (s == 0) ysh[t*33 + dl] = pc;
    }
    __syncthreads();
    for (int i = tid; i < 2048; i += 512) {
        int t = i >> 5, dj = i & 31;
        g_y[(base + t)*DD + dg*32 + dj] = ysh[t*33 + dj];
    }
}

// ============================================================
// K5: gating + out_proj + residual, NCHW write. 16 tokens / 256 threads.
// ============================================================
__global__ void k_out(const float* __restrict__ Dp, float* __restrict__ out) {
    __shared__ __align__(16) float gs[16*128];
    __shared__ float res[64*17];
    int tid = threadIdx.x;
    int t0 = blockIdx.x * 16;
    for (int i = tid; i < 2048; i += 256) {
        int tl = i >> 7, d = i & 127;
        int token = t0 + tl;
        float yv  = g_y [token*DD + d];
        float xcv = g_xc[token*DD + d];
        float zv  = g_z [token*DD + d];
        gs[i] = (yv + xcv * Dp[d]) * (zv / (1.f + __expf(-zv)));
    }
    __syncthreads();
    int c = tid & 63, tg = tid >> 6;
    float2 acc2[4];
    #pragma unroll
    for (int j = 0; j < 4; j++) acc2[j] = make_float2(0.f, 0.f);
    #pragma unroll
    for (int k4 = 0; k4 < 32; k4++) {
        float4 w4 = g_Wout4[k4*64 + c];
        float2 wA = make_float2(w4.x, w4.y);
        float2 wB = make_float2(w4.z, w4.w);
        #pragma unroll
        for (int j = 0; j < 4; j++) {
            float4 g4 = *(const float4*)(gs + (tg*4+j)*128 + k4*4);
            acc2[j] = ffma2(acc2[j], make_float2(g4.x, g4.y), wA);
            acc2[j] = ffma2(acc2[j], make_float2(g4.z, g4.w), wB);
        }
    }
    #pragma unroll
    for (int j = 0; j < 4; j++)
        res[c*17 + tg*4 + j] = acc2[j].x + acc2[j].y + g_seq[(t0 + tg*4 + j)*64 + c];
    __syncthreads();
    int b = t0 >> 12, l0 = t0 & 4095;
    for (int i = tid; i < 1024; i += 256) {
        int cc = i >> 4, t = i & 15;
        out[((b*64 + cc) << 12) + l0 + t] = res[cc*17 + t];
    }
}

// ============================================================
extern "C" void kernel_launch(void* const* d_in, const int* in_sizes, int n_in,
                              void* d_out, int out_size) {
    const float* x        = (const float*)d_in[0];
    const float* dwh_w    = (const float*)d_in[1];
    const float* dwh_b    = (const float*)d_in[2];
    const float* dww_w    = (const float*)d_in[3];
    const float* dww_b    = (const float*)d_in[4];
    const float* conv_w   = (const float*)d_in[5];
    const float* conv_b   = (const float*)d_in[6];
    const float* bn_g     = (const float*)d_in[7];
    const float* bn_b     = (const float*)d_in[8];
    const float* bn_m     = (const float*)d_in[9];
    const float* bn_v     = (const float*)d_in[10];
    const float* ln_g     = (const float*)d_in[11];
    const float* ln_b     = (const float*)d_in[12];
    const float* in_proj  = (const float*)d_in[13];
    const float* convd_w  = (const float*)d_in[14];
    const float* convd_b  = (const float*)d_in[15];
    const float* x_proj   = (const float*)d_in[16];
    const float* dt_proj_w= (const float*)d_in[17];
    const float* dt_proj_b= (const float*)d_in[18];
    const float* A_log    = (const float*)d_in[19];
    const float* Dp       = (const float*)d_in[20];
    const float* out_proj = (const float*)d_in[21];
    float* out = (float*)d_out;

    k_prep  <<<16,       256>>>(in_proj, out_proj);
    k_front <<<BB*LL/16, 256>>>(x, dwh_w, dwh_b, dww_w, dww_b,
                                conv_w, conv_b, bn_g, bn_b, bn_m, bn_v, ln_g, ln_b);
    k_conv1d<<<BB*LL/32, 256>>>(x_proj, convd_w, convd_b, dt_proj_w, dt_proj_b);
    k_scan1 <<<BB*NCH*4, 512>>>(A_log);
    k_scan2 <<<32,       256>>>();
    k_scan3 <<<BB*NCH*4, 512>>>(A_log);
    k_out   <<<BB*LL/16, 256>>>(Dp, out);
}

// round 6
// speedup vs baseline: 6.8626x; 1.0869x over previous
#include <cuda_runtime.h>
#include <math.h>

#define BB 4
#define CC 64
#define HHH 64
#define WWW 64
#define LL 4096
#define DD 128
#define SS 16
#define NCH 64
#define TCH 64

// ---- scratch ----
__device__ float g_seq[BB*LL*CC];
__device__ float g_xm [BB*LL*DD];
__device__ float g_z  [BB*LL*DD];
__device__ float g_xc [BB*LL*DD];
__device__ float g_dt [BB*LL*DD];
__device__ float g_Bc [BB*LL*SS];
__device__ float g_Cc [BB*LL*SS];
__device__ float g_y  [BB*LL*DD];   // gated ys after scan3
__device__ float g_P  [BB*NCH*DD*SS];
__device__ float g_H  [BB*NCH*DD*SS];
__device__ float4 g_Win4 [16*256];   // [k4][n]
__device__ float4 g_Wout4[32*64];    // [k4][c]

// packed fp32x2 FMA (sm_100+; PTX-only encoding)
__device__ __forceinline__ float2 ffma2(float2 d, float2 a, float2 b) {
    unsigned long long dd = *(unsigned long long*)&d;
    unsigned long long aa = *(unsigned long long*)&a;
    unsigned long long bb = *(unsigned long long*)&b;
    asm("fma.rn.f32x2 %0, %1, %2, %0;" : "+l"(dd) : "l"(aa), "l"(bb));
    return *(float2*)&dd;
}
__device__ __forceinline__ float ex2f(float x) {
    float r; asm("ex2.approx.f32 %0, %1;" : "=f"(r) : "f"(x)); return r;
}

// ============================================================
// K0: weight re-layout (tiny)
// ============================================================
__global__ void k_prep(const float* __restrict__ in_proj, const float* __restrict__ out_proj) {
    int i = blockIdx.x * 256 + threadIdx.x;   // 4096 threads
    {
        int k4 = i >> 8, n = i & 255;
        const float* p = in_proj + n*64 + k4*4;
        g_Win4[i] = make_float4(p[0], p[1], p[2], p[3]);
    }
    if (i < 2048) {
        int k4 = i >> 6, c = i & 63;
        const float* p = out_proj + c*128 + k4*4;
        g_Wout4[i] = make_float4(p[0], p[1], p[2], p[3]);
    }
}

// ============================================================
// K1: FUSED front: axial dw-convs + 1x1 conv + BN + ReLU + LN + in_proj.
// ============================================================
__global__ void k_front(const float* __restrict__ x,
                        const float* __restrict__ whw, const float* __restrict__ whb,
                        const float* __restrict__ www, const float* __restrict__ wwb,
                        const float* __restrict__ conv_w, const float* __restrict__ conv_b,
                        const float* __restrict__ bn_g, const float* __restrict__ bn_b,
                        const float* __restrict__ bn_m, const float* __restrict__ bn_v,
                        const float* __restrict__ ln_g, const float* __restrict__ ln_b) {
    __shared__ float xs[64*55];
    __shared__ float w_sh[64*65];
    __shared__ __align__(16) float tsh[16*64];
    __shared__ __align__(16) float hs[16*64];
    __shared__ float wsum[32], wsq[32];
    int tid = threadIdx.x;
    int t0 = blockIdx.x * 16;
    int b = t0 >> 12, l0 = t0 & 4095;
    int h = l0 >> 6, w0 = l0 & 63;

    for (int i = tid; i < 64*54; i += 256) {
        int c = i / 54, rem = i % 54;
        int r = rem / 18, ww = rem % 18;
        int hr = h - 1 + r;
        int wr = w0 - 1 + ww;
        float v = 0.f;
        if (hr >= 0 && hr < 64 && wr >= 0 && wr < 64)
            v = x[(((b*64 + c)*64 + hr) << 6) + wr];
        xs[c*55 + rem] = v;
    }
    for (int i = tid; i < 4096; i += 256) {
        int outc = i >> 6, in = i & 63;
        w_sh[in*65 + outc] = conv_w[i];
    }
    __syncthreads();

    int c = tid & 63, tg = tid >> 6;
    {
        float a0 = whw[c*3+0], a1 = whw[c*3+1], a2 = whw[c*3+2];
        float b0 = www[c*3+0], b1 = www[c*3+1], b2 = www[c*3+2];
        float bias = whb[c] + wwb[c];
        const float* xr = xs + c*55;
        #pragma unroll
        for (int j = 0; j < 4; j++) {
            int wl = tg*4 + j;
            int ww = wl + 1;
            float x0  = xr[18 + ww];
            float t = x0 + bias
                + a0*xr[ww] + a1*x0 + a2*xr[36 + ww]
                + b0*xr[18 + ww - 1] + b1*x0 + b2*xr[18 + ww + 1];
            tsh[wl*64 + c] = t;
        }
    }
    __syncthreads();

    float cbv = conv_b[c];
    float2 acc2[4];
    #pragma unroll
    for (int j = 0; j < 4; j++) acc2[j] = make_float2(cbv, 0.f);
    #pragma unroll
    for (int k4 = 0; k4 < 16; k4++) {
        float2 wA = make_float2(w_sh[(k4*4+0)*65 + c], w_sh[(k4*4+1)*65 + c]);
        float2 wB = make_float2(w_sh[(k4*4+2)*65 + c], w_sh[(k4*4+3)*65 + c]);
        #pragma unroll
        for (int j = 0; j < 4; j++) {
            float4 t4 = *(const float4*)(tsh + (tg*4+j)*64 + k4*4);
            acc2[j] = ffma2(acc2[j], make_float2(t4.x, t4.y), wA);
            acc2[j] = ffma2(acc2[j], make_float2(t4.z, t4.w), wB);
        }
    }
    float bnscale = rsqrtf(bn_v[c] + 1e-5f) * bn_g[c];
    float bnm = bn_m[c], bnb = bn_b[c];
    float rr[4];
    #pragma unroll
    for (int j = 0; j < 4; j++) {
        float r = fmaxf((acc2[j].x + acc2[j].y - bnm) * bnscale + bnb, 0.f);
        rr[j] = r;
        g_seq[(t0 + tg*4 + j)*64 + c] = r;
    }
    int warp = tid >> 5;
    #pragma unroll
    for (int j = 0; j < 4; j++) {
        float s1 = rr[j], s2 = rr[j]*rr[j];
        #pragma unroll
        for (int o = 16; o; o >>= 1) {
            s1 += __shfl_xor_sync(0xffffffffu, s1, o);
            s2 += __shfl_xor_sync(0xffffffffu, s2, o);
        }
        if ((tid & 31) == 0) { wsum[j*8 + warp] = s1; wsq[j*8 + warp] = s2; }
    }
    __syncthreads();
    float lg = ln_g[c], lb = ln_b[c];
    #pragma unroll
    for (int j = 0; j < 4; j++) {
        float mu  = (wsum[j*8 + 2*tg] + wsum[j*8 + 2*tg+1]) * 0.015625f;
        float var = (wsq [j*8 + 2*tg] + wsq [j*8 + 2*tg+1]) * 0.015625f - mu*mu;
        hs[(tg*4 + j)*64 + c] = (rr[j] - mu) * rsqrtf(var + 1e-5f) * lg + lb;
    }
    __syncthreads();

    int n = tid;
    float2 in2[16];
    #pragma unroll
    for (int r = 0; r < 16; r++) in2[r] = make_float2(0.f, 0.f);
    #pragma unroll
    for (int k4 = 0; k4 < 16; k4++) {
        float4 w4 = g_Win4[k4*256 + n];
        float2 wA = make_float2(w4.x, w4.y);
        float2 wB = make_float2(w4.z, w4.w);
        #pragma unroll
        for (int r = 0; r < 16; r++) {
            float4 h4 = *(const float4*)(hs + r*64 + k4*4);
            in2[r] = ffma2(in2[r], make_float2(h4.x, h4.y), wA);
            in2[r] = ffma2(in2[r], make_float2(h4.z, h4.w), wB);
        }
    }
    if (n < 128) {
        #pragma unroll
        for (int r = 0; r < 16; r++) g_xm[(t0 + r)*DD + n] = in2[r].x + in2[r].y;
    } else {
        #pragma unroll
        for (int r = 0; r < 16; r++) g_z[(t0 + r)*DD + (n - 128)] = in2[r].x + in2[r].y;
    }
}

// ============================================================
// K3: causal dw-conv1d(k=4)+SiLU, x_proj, dt/B/C.  32 tokens / 256 threads.
// ============================================================
__global__ void k_conv1d(const float* __restrict__ xpw,
                         const float* __restrict__ cw, const float* __restrict__ cb,
                         const float* __restrict__ dpw, const float* __restrict__ dpb) {
    __shared__ __align__(16) float xpw_sh[36*128];
    __shared__ __align__(16) float xc_sh[32*132];
    __shared__ float dbc_sh[32*38];
    __shared__ __align__(16) float cw_sh[512];
    __shared__ float cb_sh[128];
    __shared__ __align__(16) float dpw_sh[512];
    __shared__ float dpb_sh[128];
    int tid = threadIdx.x;
    int t0 = blockIdx.x * 32;
    for (int i = tid; i < 4608; i += 256) xpw_sh[i] = xpw[i];
    for (int i = tid; i < 512; i += 256) { cw_sh[i] = cw[i]; dpw_sh[i] = dpw[i]; }
    if (tid < 128) { cb_sh[tid] = cb[tid]; dpb_sh[tid] = dpb[tid]; }
    __syncthreads();

    for (int i = tid; i < 32*128; i += 256) {
        int tl = i >> 7, d = i & 127;
        int token = t0 + tl;
        int l = token & 4095;
        float acc = cb_sh[d];
        #pragma unroll
        for (int j = 0; j < 4; j++) {
            int lj = l - 3 + j;
            if (lj >= 0) acc += cw_sh[d*4+j] * g_xm[(token - 3 + j)*DD + d];
        }
        float v = acc / (1.f + __expf(-acc));
        xc_sh[tl*132 + d] = v;
        g_xc[token*DD + d] = v;
    }
    __syncthreads();

    {
        int tl = tid & 31, eb = tid >> 5;
        float2 acc[5];
        #pragma unroll
        for (int ii = 0; ii < 5; ii++) acc[ii] = make_float2(0.f, 0.f);
        const float4* xc4 = (const float4*)(xc_sh + tl*132);
        #pragma unroll
        for (int k4 = 0; k4 < 32; k4++) {
            float4 xv = xc4[k4];
            float2 xA = make_float2(xv.x, xv.y);
            float2 xB = make_float2(xv.z, xv.w);
            #pragma unroll
            for (int ii = 0; ii < 5; ii++) {
                int e = eb + ii*8;
                if (e < 36) {
                    float4 wv = *(const float4*)(xpw_sh + e*128 + k4*4);
                    acc[ii] = ffma2(acc[ii], xA, make_float2(wv.x, wv.y));
                    acc[ii] = ffma2(acc[ii], xB, make_float2(wv.z, wv.w));
                }
            }
        }
        #pragma unroll
        for (int ii = 0; ii < 5; ii++) {
            int e = eb + ii*8;
            if (e < 36) dbc_sh[tl*38 + e] = acc[ii].x + acc[ii].y;
        }
    }
    __syncthreads();

    for (int i = tid; i < 32*128; i += 256) {
        int tl = i >> 7, d = i & 127;
        float4 dp4 = *(const float4*)(dpw_sh + d*4);
        const float* db = dbc_sh + tl*38;
        float tv = dpb_sh[d] + db[0]*dp4.x + db[1]*dp4.y + db[2]*dp4.z + db[3]*dp4.w;
        float dtv = (tv > 20.f) ? tv : log1pf(__expf(tv));
        g_dt[(t0 + tl)*DD + d] = dtv;
    }
    for (int i = tid; i < 512; i += 256) {
        int tl = i >> 4, s = i & 15;
        g_Bc[(t0 + tl)*SS + s] = dbc_sh[tl*38 + 4 + s];
        g_Cc[(t0 + tl)*SS + s] = dbc_sh[tl*38 + 20 + s];
    }
}

// ============================================================
// K4a: scan phase 1 — packed (dt, dt*xc) in shared; 7-inst inner step.
// ============================================================
__global__ void k_scan1(const float* __restrict__ A_log) {
    __shared__ __align__(16) float2 dtw[64*32];   // (dt, dt*xc)
    __shared__ float Bs[64*16];
    int tid = threadIdx.x;
    int bc = blockIdx.x >> 2;
    int dg = blockIdx.x & 3;
    int dl = tid >> 4, s = tid & 15;
    int d = dg*32 + dl;
    int b = bc >> 6, chunk = bc & 63;
    int base = (b << 12) + (chunk << 6);
    for (int i = tid; i < 2048; i += 512) {
        int t = i >> 5, dj = i & 31;
        float dtv = g_dt[(base + t)*DD + dg*32 + dj];
        float xcv = g_xc[(base + t)*DD + dg*32 + dj];
        dtw[i] = make_float2(dtv, dtv * xcv);
    }
    for (int i = tid; i < 1024; i += 512) Bs[i] = g_Bc[base*SS + i];
    float A2 = -__expf(A_log[d*SS + s]) * 1.4426950408889634f;
    __syncthreads();
    float h = 0.f, P = 1.f;
    #pragma unroll 8
    for (int t = 0; t < TCH; t++) {
        float2 dw = dtw[t*32 + dl];
        float a = ex2f(dw.x * A2);
        h = h * a + dw.y * Bs[t*16 + s];
        P *= a;
    }
    int idx = (bc*DD + d)*SS + s;
    g_P[idx] = P;
    g_H[idx] = h;
}

// ============================================================
// K4b: scan phase 2 — explicit 8-wide MLP batching.
// ============================================================
__global__ void k_scan2() {
    int gid = blockIdx.x * blockDim.x + threadIdx.x;   // 0..8191
    int b  = gid >> 11;
    int ds = gid & 2047;
    const float* Pp = g_P + b*NCH*2048 + ds;
    float*       Hp = g_H + b*NCH*2048 + ds;
    float H = 0.f;
    #pragma unroll
    for (int g = 0; g < 8; g++) {
        float p[8], hh[8];
        #pragma unroll
        for (int j = 0; j < 8; j++) {
            p[j]  = __ldg(Pp + (g*8 + j)*2048);
            hh[j] = __ldg(Hp + (g*8 + j)*2048);
        }
        #pragma unroll
        for (int j = 0; j < 8; j++) {
            float Hs = H;
            H = p[j]*H + hh[j];
            Hp[(g*8 + j)*2048] = Hs;
        }
    }
}

// ============================================================
// K4c: scan phase 3 — packed (dt, dt*xc), fused gating epilogue.
// ============================================================
__global__ void k_scan3(const float* __restrict__ A_log, const float* __restrict__ Dp) {
    __shared__ __align__(16) float2 dtw[64*32];
    __shared__ float Bs[64*16], Cs[64*16];
    __shared__ float ysh[64*33];
    int tid = threadIdx.x;
    int bc = blockIdx.x >> 2;
    int dg = blockIdx.x & 3;
    int dl = tid >> 4, s = tid & 15;
    int d = dg*32 + dl;
    int b = bc >> 6, chunk = bc & 63;
    int base = (b << 12) + (chunk << 6);
    for (int i = tid; i < 2048; i += 512) {
        int t = i >> 5, dj = i & 31;
        float dtv = g_dt[(base + t)*DD + dg*32 + dj];
        float xcv = g_xc[(base + t)*DD + dg*32 + dj];
        dtw[i] = make_float2(dtv, dtv * xcv);
    }
    for (int i = tid; i < 1024; i += 512) {
        Bs[i] = g_Bc[base*SS + i];
        Cs[i] = g_Cc[base*SS + i];
    }
    float A2 = -__expf(A_log[d*SS + s]) * 1.4426950408889634f;
    float h = g_H[(bc*DD + d)*SS + s];
    __syncthreads();
    #pragma unroll 4
    for (int t = 0; t < TCH; t++) {
        float2 dw = dtw[t*32 + dl];
        float a = ex2f(dw.x * A2);
        h = h * a + dw.y * Bs[t*16 + s];
        float pc = h * Cs[t*16 + s];
        pc += __shfl_xor_sync(0xffffffffu, pc, 1);
        pc += __shfl_xor_sync(0xffffffffu, pc, 2);
        pc += __shfl_xor_sync(0xffffffffu, pc, 4);
        pc += __shfl_xor_sync(0xffffffffu, pc, 8);
        if (s == 0) ysh[t*33 + dl] = pc;
    }
    __syncthreads();
    // fused gating: g_y <- (y + xc*Dp) * silu(z)
    float Dpv = Dp[dg*32 + (tid & 31)];
    for (int i = tid; i < 2048; i += 512) {
        int t = i >> 5, dj = i & 31;
        int gi = (base + t)*DD + dg*32 + dj;
        float yv  = ysh[t*33 + dj];
        float xcv = g_xc[gi];
        float zv  = g_z [gi];
        float sil = zv / (1.f + __expf(-zv));
        g_y[gi] = (yv + xcv * Dpv) * sil;
    }
}

// ============================================================
// K5: out_proj GEMM + residual, NCHW write. 16 tokens / 256 threads.
// ============================================================
__global__ void k_out(float* __restrict__ out) {
    __shared__ __align__(16) float gs[16*128];
    __shared__ float res[64*17];
    int tid = threadIdx.x;
    int t0 = blockIdx.x * 16;
    for (int i = tid; i < 2048; i += 256) gs[i] = g_y[t0*DD + i];
    __syncthreads();
    int c = tid & 63, tg = tid >> 6;
    float2 acc2[4];
    #pragma unroll
    for (int j = 0; j < 4; j++) acc2[j] = make_float2(0.f, 0.f);
    #pragma unroll
    for (int k4 = 0; k4 < 32; k4++) {
        float4 w4 = g_Wout4[k4*64 + c];
        float2 wA = make_float2(w4.x, w4.y);
        float2 wB = make_float2(w4.z, w4.w);
        #pragma unroll
        for (int j = 0; j < 4; j++) {
            float4 g4 = *(const float4*)(gs + (tg*4+j)*128 + k4*4);
            acc2[j] = ffma2(acc2[j], make_float2(g4.x, g4.y), wA);
            acc2[j] = ffma2(acc2[j], make_float2(g4.z, g4.w), wB);
        }
    }
    #pragma unroll
    for (int j = 0; j < 4; j++)
        res[c*17 + tg*4 + j] = acc2[j].x + acc2[j].y + g_seq[(t0 + tg*4 + j)*64 + c];
    __syncthreads();
    int b = t0 >> 12, l0 = t0 & 4095;
    for (int i = tid; i < 1024; i += 256) {
        int cc = i >> 4, t = i & 15;
        out[((b*64 + cc) << 12) + l0 + t] = res[cc*17 + t];
    }
}

// ============================================================
extern "C" void kernel_launch(void* const* d_in, const int* in_sizes, int n_in,
                              void* d_out, int out_size) {
    const float* x        = (const float*)d_in[0];
    const float* dwh_w    = (const float*)d_in[1];
    const float* dwh_b    = (const float*)d_in[2];
    const float* dww_w    = (const float*)d_in[3];
    const float* dww_b    = (const float*)d_in[4];
    const float* conv_w   = (const float*)d_in[5];
    const float* conv_b   = (const float*)d_in[6];
    const float* bn_g     = (const float*)d_in[7];
    const float* bn_b     = (const float*)d_in[8];
    const float* bn_m     = (const float*)d_in[9];
    const float* bn_v     = (const float*)d_in[10];
    const float* ln_g     = (const float*)d_in[11];
    const float* ln_b     = (const float*)d_in[12];
    const float* in_proj  = (const float*)d_in[13];
    const float* convd_w  = (const float*)d_in[14];
    const float* convd_b  = (const float*)d_in[15];
    const float* x_proj   = (const float*)d_in[16];
    const float* dt_proj_w= (const float*)d_in[17];
    const float* dt_proj_b= (const float*)d_in[18];
    const float* A_log    = (const float*)d_in[19];
    const float* Dp       = (const float*)d_in[20];
    const float* out_proj = (const float*)d_in[21];
    float* out = (float*)d_out;

    k_prep  <<<16,       256>>>(in_proj, out_proj);
    k_front <<<BB*LL/16, 256>>>(x, dwh_w, dwh_b, dww_w, dww_b,
                                conv_w, conv_b, bn_g, bn_b, bn_m, bn_v, ln_g, ln_b);
    k_conv1d<<<BB*LL/32, 256>>>(x_proj, convd_w, convd_b, dt_proj_w, dt_proj_b);
    k_scan1 <<<BB*NCH*4, 512>>>(A_log);
    k_scan2 <<<32,       256>>>();
    k_scan3 <<<BB*NCH*4, 512>>>(A_log, Dp);
    k_out   <<<BB*LL/16, 256>>>(out);
}

// round 8
// speedup vs baseline: 7.9494x; 1.1584x over previous
#include <cuda_runtime.h>
#include <math.h>

#define BB 4
#define CC 64
#define HHH 64
#define WWW 64
#define LL 4096
#define DD 128
#define SS 16
#define NCH 64
#define TCH 64

// ---- scratch ----
__device__ float g_seq[BB*LL*CC];
__device__ float g_xm [BB*LL*DD];
__device__ float g_z  [BB*LL*DD];
__device__ float g_xc [BB*LL*DD];
__device__ float g_dt [BB*LL*DD];
__device__ float g_Bc [BB*LL*SS];
__device__ float g_Cc [BB*LL*SS];
__device__ float g_y  [BB*LL*DD];   // raw scan ys (gating applied in k_out)
__device__ float g_P  [BB*NCH*DD*SS];
__device__ float g_H  [BB*NCH*DD*SS];
__device__ float4 g_Win4 [16*256];   // [k4][n]
__device__ float4 g_Wout4[32*64];    // [k4][c]

// packed fp32x2 FMA (sm_100+; PTX-only encoding)
__device__ __forceinline__ float2 ffma2(float2 d, float2 a, float2 b) {
    unsigned long long dd = *(unsigned long long*)&d;
    unsigned long long aa = *(unsigned long long*)&a;
    unsigned long long bb = *(unsigned long long*)&b;
    asm("fma.rn.f32x2 %0, %1, %2, %0;" : "+l"(dd) : "l"(aa), "l"(bb));
    return *(float2*)&dd;
}
__device__ __forceinline__ float ex2f(float x) {
    float r; asm("ex2.approx.f32 %0, %1;" : "=f"(r) : "f"(x)); return r;
}

// ============================================================
// K0: weight re-layout (tiny)
// ============================================================
__global__ void k_prep(const float* __restrict__ in_proj, const float* __restrict__ out_proj) {
    int i = blockIdx.x * 256 + threadIdx.x;   // 4096 threads
    {
        int k4 = i >> 8, n = i & 255;
        const float* p = in_proj + n*64 + k4*4;
        g_Win4[i] = make_float4(p[0], p[1], p[2], p[3]);
    }
    if (i < 2048) {
        int k4 = i >> 6, c = i & 63;
        const float* p = out_proj + c*128 + k4*4;
        g_Wout4[i] = make_float4(p[0], p[1], p[2], p[3]);
    }
}

// ============================================================
// K1: FUSED front: axial dw-convs + 1x1 conv + BN + ReLU + LN + in_proj.
// ============================================================
__global__ void k_front(const float* __restrict__ x,
                        const float* __restrict__ whw, const float* __restrict__ whb,
                        const float* __restrict__ www, const float* __restrict__ wwb,
                        const float* __restrict__ conv_w, const float* __restrict__ conv_b,
                        const float* __restrict__ bn_g, const float* __restrict__ bn_b,
                        const float* __restrict__ bn_m, const float* __restrict__ bn_v,
                        const float* __restrict__ ln_g, const float* __restrict__ ln_b) {
    __shared__ float xs[64*55];
    __shared__ float w_sh[64*65];
    __shared__ __align__(16) float tsh[16*64];
    __shared__ __align__(16) float hs[16*64];
    __shared__ float wsum[32], wsq[32];
    int tid = threadIdx.x;
    int t0 = blockIdx.x * 16;
    int b = t0 >> 12, l0 = t0 & 4095;
    int h = l0 >> 6, w0 = l0 & 63;

    for (int i = tid; i < 64*54; i += 256) {
        int c = i / 54, rem = i % 54;
        int r = rem / 18, ww = rem % 18;
        int hr = h - 1 + r;
        int wr = w0 - 1 + ww;
        float v = 0.f;
        if (hr >= 0 && hr < 64 && wr >= 0 && wr < 64)
            v = x[(((b*64 + c)*64 + hr) << 6) + wr];
        xs[c*55 + rem] = v;
    }
    for (int i = tid; i < 4096; i += 256) {
        int outc = i >> 6, in = i & 63;
        w_sh[in*65 + outc] = conv_w[i];
    }
    __syncthreads();

    int c = tid & 63, tg = tid >> 6;
    {
        float a0 = whw[c*3+0], a1 = whw[c*3+1], a2 = whw[c*3+2];
        float b0 = www[c*3+0], b1 = www[c*3+1], b2 = www[c*3+2];
        float bias = whb[c] + wwb[c];
        const float* xr = xs + c*55;
        #pragma unroll
        for (int j = 0; j < 4; j++) {
            int wl = tg*4 + j;
            int ww = wl + 1;
            float x0  = xr[18 + ww];
            float t = x0 + bias
                + a0*xr[ww] + a1*x0 + a2*xr[36 + ww]
                + b0*xr[18 + ww - 1] + b1*x0 + b2*xr[18 + ww + 1];
            tsh[wl*64 + c] = t;
        }
    }
    __syncthreads();

    float cbv = conv_b[c];
    float2 acc2[4];
    #pragma unroll
    for (int j = 0; j < 4; j++) acc2[j] = make_float2(cbv, 0.f);
    #pragma unroll
    for (int k4 = 0; k4 < 16; k4++) {
        float2 wA = make_float2(w_sh[(k4*4+0)*65 + c], w_sh[(k4*4+1)*65 + c]);
        float2 wB = make_float2(w_sh[(k4*4+2)*65 + c], w_sh[(k4*4+3)*65 + c]);
        #pragma unroll
        for (int j = 0; j < 4; j++) {
            float4 t4 = *(const float4*)(tsh + (tg*4+j)*64 + k4*4);
            acc2[j] = ffma2(acc2[j], make_float2(t4.x, t4.y), wA);
            acc2[j] = ffma2(acc2[j], make_float2(t4.z, t4.w), wB);
        }
    }
    float bnscale = rsqrtf(bn_v[c] + 1e-5f) * bn_g[c];
    float bnm = bn_m[c], bnb = bn_b[c];
    float rr[4];
    #pragma unroll
    for (int j = 0; j < 4; j++) {
        float r = fmaxf((acc2[j].x + acc2[j].y - bnm) * bnscale + bnb, 0.f);
        rr[j] = r;
        g_seq[(t0 + tg*4 + j)*64 + c] = r;
    }
    int warp = tid >> 5;
    #pragma unroll
    for (int j = 0; j < 4; j++) {
        float s1 = rr[j], s2 = rr[j]*rr[j];
        #pragma unroll
        for (int o = 16; o; o >>= 1) {
            s1 += __shfl_xor_sync(0xffffffffu, s1, o);
            s2 += __shfl_xor_sync(0xffffffffu, s2, o);
        }
        if ((tid & 31) == 0) { wsum[j*8 + warp] = s1; wsq[j*8 + warp] = s2; }
    }
    __syncthreads();
    float lg = ln_g[c], lb = ln_b[c];
    #pragma unroll
    for (int j = 0; j < 4; j++) {
        float mu  = (wsum[j*8 + 2*tg] + wsum[j*8 + 2*tg+1]) * 0.015625f;
        float var = (wsq [j*8 + 2*tg] + wsq [j*8 + 2*tg+1]) * 0.015625f - mu*mu;
        hs[(tg*4 + j)*64 + c] = (rr[j] - mu) * rsqrtf(var + 1e-5f) * lg + lb;
    }
    __syncthreads();

    int n = tid;
    float2 in2[16];
    #pragma unroll
    for (int r = 0; r < 16; r++) in2[r] = make_float2(0.f, 0.f);
    #pragma unroll
    for (int k4 = 0; k4 < 16; k4++) {
        float4 w4 = g_Win4[k4*256 + n];
        float2 wA = make_float2(w4.x, w4.y);
        float2 wB = make_float2(w4.z, w4.w);
        #pragma unroll
        for (int r = 0; r < 16; r++) {
            float4 h4 = *(const float4*)(hs + r*64 + k4*4);
            in2[r] = ffma2(in2[r], make_float2(h4.x, h4.y), wA);
            in2[r] = ffma2(in2[r], make_float2(h4.z, h4.w), wB);
        }
    }
    if (n < 128) {
        #pragma unroll
        for (int r = 0; r < 16; r++) g_xm[(t0 + r)*DD + n] = in2[r].x + in2[r].y;
    } else {
        #pragma unroll
        for (int r = 0; r < 16; r++) g_z[(t0 + r)*DD + (n - 128)] = in2[r].x + in2[r].y;
    }
}

// ============================================================
// K3: causal dw-conv1d(k=4)+SiLU, x_proj, dt/B/C.  32 tokens / 256 threads.
// ============================================================
__global__ void k_conv1d(const float* __restrict__ xpw,
                         const float* __restrict__ cw, const float* __restrict__ cb,
                         const float* __restrict__ dpw, const float* __restrict__ dpb) {
    __shared__ __align__(16) float xpw_sh[36*128];
    __shared__ __align__(16) float xc_sh[32*132];
    __shared__ float dbc_sh[32*38];
    __shared__ __align__(16) float cw_sh[512];
    __shared__ float cb_sh[128];
    __shared__ __align__(16) float dpw_sh[512];
    __shared__ float dpb_sh[128];
    int tid = threadIdx.x;
    int t0 = blockIdx.x * 32;
    for (int i = tid; i < 4608; i += 256) xpw_sh[i] = xpw[i];
    for (int i = tid; i < 512; i += 256) { cw_sh[i] = cw[i]; dpw_sh[i] = dpw[i]; }
    if (tid < 128) { cb_sh[tid] = cb[tid]; dpb_sh[tid] = dpb[tid]; }
    __syncthreads();

    for (int i = tid; i < 32*128; i += 256) {
        int tl = i >> 7, d = i & 127;
        int token = t0 + tl;
        int l = token & 4095;
        float acc = cb_sh[d];
        #pragma unroll
        for (int j = 0; j < 4; j++) {
            int lj = l - 3 + j;
            if (lj >= 0) acc += cw_sh[d*4+j] * g_xm[(token - 3 + j)*DD + d];
        }
        float v = acc / (1.f + __expf(-acc));
        xc_sh[tl*132 + d] = v;
        g_xc[token*DD + d] = v;
    }
    __syncthreads();

    {
        int tl = tid & 31, eb = tid >> 5;
        float2 acc[5];
        #pragma unroll
        for (int ii = 0; ii < 5; ii++) acc[ii] = make_float2(0.f, 0.f);
        const float4* xc4 = (const float4*)(xc_sh + tl*132);
        #pragma unroll
        for (int k4 = 0; k4 < 32; k4++) {
            float4 xv = xc4[k4];
            float2 xA = make_float2(xv.x, xv.y);
            float2 xB = make_float2(xv.z, xv.w);
            #pragma unroll
            for (int ii = 0; ii < 5; ii++) {
                int e = eb + ii*8;
                if (e < 36) {
                    float4 wv = *(const float4*)(xpw_sh + e*128 + k4*4);
                    acc[ii] = ffma2(acc[ii], xA, make_float2(wv.x, wv.y));
                    acc[ii] = ffma2(acc[ii], xB, make_float2(wv.z, wv.w));
                }
            }
        }
        #pragma unroll
        for (int ii = 0; ii < 5; ii++) {
            int e = eb + ii*8;
            if (e < 36) dbc_sh[tl*38 + e] = acc[ii].x + acc[ii].y;
        }
    }
    __syncthreads();

    for (int i = tid; i < 32*128; i += 256) {
        int tl = i >> 7, d = i & 127;
        float4 dp4 = *(const float4*)(dpw_sh + d*4);
        const float* db = dbc_sh + tl*38;
        float tv = dpb_sh[d] + db[0]*dp4.x + db[1]*dp4.y + db[2]*dp4.z + db[3]*dp4.w;
        float dtv = (tv > 20.f) ? tv : log1pf(__expf(tv));
        g_dt[(t0 + tl)*DD + d] = dtv;
    }
    for (int i = tid; i < 512; i += 256) {
        int tl = i >> 4, s = i & 15;
        g_Bc[(t0 + tl)*SS + s] = dbc_sh[tl*38 + 4 + s];
        g_Cc[(t0 + tl)*SS + s] = dbc_sh[tl*38 + 20 + s];
    }
}

// ============================================================
// K4a: scan phase 1 — s-quad per thread. 256 thr = 64 d x 4 quads.
// Grid = B*NCH*2 (d-halves).
// ============================================================
__global__ void k_scan1(const float* __restrict__ A_log) {
    __shared__ __align__(16) float2 dtw[64*64];   // [t][dl] (dt, dt*xc)  32KB
    __shared__ __align__(16) float Bs[64*16];     // 4KB
    int tid = threadIdx.x;            // 256
    int bc = blockIdx.x >> 1;
    int half = blockIdx.x & 1;
    int q = tid & 3, dl = tid >> 2;
    int d = half*64 + dl;
    int b = bc >> 6, chunk = bc & 63;
    int base = (b << 12) + (chunk << 6);
    for (int i = tid; i < 4096; i += 256) {
        int t = i >> 6, dj = i & 63;
        float dtv = g_dt[(base + t)*DD + half*64 + dj];
        float xcv = g_xc[(base + t)*DD + half*64 + dj];
        dtw[i] = make_float2(dtv, dtv * xcv);
    }
    for (int i = tid; i < 1024; i += 256) Bs[i] = g_Bc[base*SS + i];
    const float L2E = 1.4426950408889634f;
    float4 al = *(const float4*)(A_log + d*SS + q*4);
    float A0 = -__expf(al.x)*L2E, A1 = -__expf(al.y)*L2E;
    float A2_ = -__expf(al.z)*L2E, A3 = -__expf(al.w)*L2E;
    __syncthreads();
    float h0=0.f, h1=0.f, h2=0.f, h3=0.f, sdt=0.f;
    #pragma unroll 8
    for (int t = 0; t < TCH; t++) {
        float2 dw = dtw[t*64 + dl];
        float4 b4 = *(const float4*)(Bs + t*16 + q*4);
        float a0 = ex2f(dw.x*A0), a1 = ex2f(dw.x*A1);
        float a2 = ex2f(dw.x*A2_), a3 = ex2f(dw.x*A3);
        h0 = h0*a0 + dw.y*b4.x;
        h1 = h1*a1 + dw.y*b4.y;
        h2 = h2*a2 + dw.y*b4.z;
        h3 = h3*a3 + dw.y*b4.w;
        sdt += dw.x;
    }
    int idx = (bc*DD + d)*4 + q;    // float4 units
    ((float4*)g_P)[idx] = make_float4(ex2f(A0*sdt), ex2f(A1*sdt), ex2f(A2_*sdt), ex2f(A3*sdt));
    ((float4*)g_H)[idx] = make_float4(h0, h1, h2, h3);
}

// ============================================================
// K4b: scan phase 2 — explicit 8-wide MLP batching.
// ============================================================
__global__ void k_scan2() {
    int gid = blockIdx.x * blockDim.x + threadIdx.x;   // 0..8191
    int b  = gid >> 11;
    int ds = gid & 2047;
    const float* Pp = g_P + b*NCH*2048 + ds;
    float*       Hp = g_H + b*NCH*2048 + ds;
    float H = 0.f;
    #pragma unroll
    for (int g = 0; g < 8; g++) {
        float p[8], hh[8];
        #pragma unroll
        for (int j = 0; j < 8; j++) {
            p[j]  = __ldg(Pp + (g*8 + j)*2048);
            hh[j] = __ldg(Hp + (g*8 + j)*2048);
        }
        #pragma unroll
        for (int j = 0; j < 8; j++) {
            float Hs = H;
            H = p[j]*H + hh[j];
            Hp[(g*8 + j)*2048] = Hs;
        }
    }
}

// ============================================================
// K4c: scan phase 3 — s-quad per thread, quad shuffle-reduce, direct y store.
// ============================================================
__global__ void k_scan3(const float* __restrict__ A_log) {
    __shared__ __align__(16) float2 dtw[64*64];   // 32KB
    __shared__ __align__(16) float Bs[64*16];     // 4KB
    __shared__ __align__(16) float Cs[64*16];     // 4KB
    int tid = threadIdx.x;            // 256
    int bc = blockIdx.x >> 1;
    int half = blockIdx.x & 1;
    int q = tid & 3, dl = tid >> 2;
    int d = half*64 + dl;
    int b = bc >> 6, chunk = bc & 63;
    int base = (b << 12) + (chunk << 6);
    for (int i = tid; i < 4096; i += 256) {
        int t = i >> 6, dj = i & 63;
        float dtv = g_dt[(base + t)*DD + half*64 + dj];
        float xcv = g_xc[(base + t)*DD + half*64 + dj];
        dtw[i] = make_float2(dtv, dtv * xcv);
    }
    for (int i = tid; i < 1024; i += 256) {
        Bs[i] = g_Bc[base*SS + i];
        Cs[i] = g_Cc[base*SS + i];
    }
    const float L2E = 1.4426950408889634f;
    float4 al = *(const float4*)(A_log + d*SS + q*4);
    float A0 = -__expf(al.x)*L2E, A1 = -__expf(al.y)*L2E;
    float A2_ = -__expf(al.z)*L2E, A3 = -__expf(al.w)*L2E;
    float4 h4 = ((const float4*)g_H)[(bc*DD + d)*4 + q];
    float h0 = h4.x, h1 = h4.y, h2 = h4.z, h3 = h4.w;
    __syncthreads();
    float* yout = g_y + base*DD + d;
    #pragma unroll 4
    for (int t = 0; t < TCH; t++) {
        float2 dw = dtw[t*64 + dl];
        float4 b4 = *(const float4*)(Bs + t*16 + q*4);
        float4 c4 = *(const float4*)(Cs + t*16 + q*4);
        float a0 = ex2f(dw.x*A0), a1 = ex2f(dw.x*A1);
        float a2 = ex2f(dw.x*A2_), a3 = ex2f(dw.x*A3);
        h0 = h0*a0 + dw.y*b4.x;
        h1 = h1*a1 + dw.y*b4.y;
        h2 = h2*a2 + dw.y*b4.z;
        h3 = h3*a3 + dw.y*b4.w;
        float pc = h0*c4.x + h1*c4.y + h2*c4.z + h3*c4.w;
        pc += __shfl_xor_sync(0xffffffffu, pc, 1);
        pc += __shfl_xor_sync(0xffffffffu, pc, 2);
        if (q == 0) yout[t*DD] = pc;
    }
}

// ============================================================
// K5: gating + out_proj GEMM + residual, NCHW write. 16 tokens / 256 threads.
// ============================================================
__global__ void k_out(const float* __restrict__ Dp, float* __restrict__ out) {
    __shared__ __align__(16) float gs[16*128];
    __shared__ float res[64*17];
    __shared__ float dp_sh[128];
    int tid = threadIdx.x;
    int t0 = blockIdx.x * 16;
    if (tid < 128) dp_sh[tid] = Dp[tid];
    __syncthreads();
    for (int i = tid; i < 2048; i += 256) {
        int d = i & 127;
        float yv  = g_y [t0*DD + i];
        float xcv = g_xc[t0*DD + i];
        float zv  = g_z [t0*DD + i];
        float sil = zv / (1.f + __expf(-zv));
        gs[i] = (yv + xcv * dp_sh[d]) * sil;
    }
    __syncthreads();
    int c = tid & 63, tg = tid >> 6;
    float2 acc2[4];
    #pragma unroll
    for (int j = 0; j < 4; j++) acc2[j] = make_float2(0.f, 0.f);
    #pragma unroll
    for (int k4 = 0; k4 < 32; k4++) {
        float4 w4 = g_Wout4[k4*64 + c];
        float2 wA = make_float2(w4.x, w4.y);
        float2 wB = make_float2(w4.z, w4.w);
        #pragma unroll
        for (int j = 0; j < 4; j++) {
            float4 g4 = *(const float4*)(gs + (tg*4+j)*128 + k4*4);
            acc2[j] = ffma2(acc2[j], make_float2(g4.x, g4.y), wA);
            acc2[j] = ffma2(acc2[j], make_float2(g4.z, g4.w), wB);
        }
    }
    #pragma unroll
    for (int j = 0; j < 4; j++)
        res[c*17 + tg*4 + j] = acc2[j].x + acc2[j].y + g_seq[(t0 + tg*4 + j)*64 + c];
    __syncthreads();
    int b = t0 >> 12, l0 = t0 & 4095;
    for (int i = tid; i < 1024; i += 256) {
        int cc = i >> 4, t = i & 15;
        out[((b*64 + cc) << 12) + l0 + t] = res[cc*17 + t];
    }
}

// ============================================================
extern "C" void kernel_launch(void* const* d_in, const int* in_sizes, int n_in,
                              void* d_out, int out_size) {
    const float* x        = (const float*)d_in[0];
    const float* dwh_w    = (const float*)d_in[1];
    const float* dwh_b    = (const float*)d_in[2];
    const float* dww_w    = (const float*)d_in[3];
    const float* dww_b    = (const float*)d_in[4];
    const float* conv_w   = (const float*)d_in[5];
    const float* conv_b   = (const float*)d_in[6];
    const float* bn_g     = (const float*)d_in[7];
    const float* bn_b     = (const float*)d_in[8];
    const float* bn_m     = (const float*)d_in[9];
    const float* bn_v     = (const float*)d_in[10];
    const float* ln_g     = (const float*)d_in[11];
    const float* ln_b     = (const float*)d_in[12];
    const float* in_proj  = (const float*)d_in[13];
    const float* convd_w  = (const float*)d_in[14];
    const float* convd_b  = (const float*)d_in[15];
    const float* x_proj   = (const float*)d_in[16];
    const float* dt_proj_w= (const float*)d_in[17];
    const float* dt_proj_b= (const float*)d_in[18];
    const float* A_log    = (const float*)d_in[19];
    const float* Dp       = (const float*)d_in[20];
    const float* out_proj = (const float*)d_in[21];
    float* out = (float*)d_out;

    k_prep  <<<16,       256>>>(in_proj, out_proj);
    k_front <<<BB*LL/16, 256>>>(x, dwh_w, dwh_b, dww_w, dww_b,
                                conv_w, conv_b, bn_g, bn_b, bn_m, bn_v, ln_g, ln_b);
    k_conv1d<<<BB*LL/32, 256>>>(x_proj, convd_w, convd_b, dt_proj_w, dt_proj_b);
    k_scan1 <<<BB*NCH*2, 256>>>(A_log);
    k_scan2 <<<32,       256>>>();
    k_scan3 <<<BB*NCH*2, 256>>>(A_log);
    k_out   <<<BB*LL/16, 256>>>(Dp, out);
}